// round 15
// baseline (speedup 1.0000x reference)
#include <cuda_runtime.h>
#include <cuda_fp16.h>
#include <cstdint>

#define TT 500
#define BB 256
#define NI 128
#define H1 512
#define H2 256
#define NB1 16

#define BETA1 0.81873075307798182f
#define BETA2 0.90483741803595952f
#define INV2048 4.8828125e-4f

// ---------------- device scratch (static, no allocations) ----------------
__device__ __align__(16) __half g_w1hi[H1 * NI];
__device__ __align__(16) __half g_w1lo[H1 * NI];
__device__ unsigned  g_bits[TT * BB * NB1];           // spk1 bitmasks
__device__ float     g_s1cnt[BB * H1];
__device__ float     g_m2sum[BB * H2];
__device__ float     g_s2cnt[BB * H2];
__device__ float     g_cur1[(size_t)TT * BB * H1];    // dense currents layer1 (262 MB)
__device__ float     g_cur2[(size_t)TT * BB * H2];

#define CP_ASYNC16(dst, src) asm volatile("cp.async.cg.shared.global [%0], [%1], 16;" :: "r"(dst), "l"(src))
#define CP_COMMIT()          asm volatile("cp.async.commit_group;")
#define CP_WAIT1()           asm volatile("cp.async.wait_group 1;")
#define CP_WAIT0()           asm volatile("cp.async.wait_group 0;")

// ---------------- K0: W1 -> hi/lo fp16 split ----------------
__global__ void k_wprep(const float* __restrict__ W1) {
    int i = blockIdx.x * blockDim.x + threadIdx.x;
    if (i >= H1 * NI) return;
    float w = W1[i];
    __half hi = __float2half_rn(w);
    float lo = (w - __half2float(hi)) * 2048.f;
    g_w1hi[i] = hi;
    g_w1lo[i] = __float2half_rn(lo);
}

// ---------------- K1mm: dense fp16-MMA GEMM -> cur1 (persistent) ----------
// grid = 296 persistent blocks (2/SM), item = (bp, chunk) strided; 1024 items.
// Per item: M=128 rows (2b x 64t); 8 nb of N=64; B rows 0-63 hi / 64-127 lo.
// smem: A 128x136 h | B[2] 128x136 h  = 104448 B -> 2 blocks/SM
#define PA 136
#define SM_A   0
#define SM_B0  34816
#define SM_B1  69632
#define SMEM1  104448
#define K1GRID 296

__global__ void __launch_bounds__(256, 2) k1_mm(const float* __restrict__ spikes) {
    extern __shared__ char smc[];
    __half* As = (__half*)(smc + SM_A);

    int tid  = threadIdx.x;
    int lane = tid & 31;
    int warp = tid >> 5;

    int wm = (warp & 3) * 32;
    int wn = (warp >> 2) * 32;
    int ra = lane & 15, ca = lane >> 4;
    int rb = (lane & 7) + ((lane >> 3) & 1) * 8;
    int cb = (lane >> 4) * 8;

    uint32_t sA  = (uint32_t)__cvta_generic_to_shared(As);
    uint32_t sB0 = (uint32_t)__cvta_generic_to_shared(smc + SM_B0);
    uint32_t sB1 = (uint32_t)__cvta_generic_to_shared(smc + SM_B1);

    for (int item = blockIdx.x; item < 1024; item += K1GRID) {
        int bp    = item >> 3;
        int chunk = item & 7;
        int b0 = bp * 2;
        int t0 = chunk * 64;

        // build A: 128 rows (2b x 64t) x 128 halves, spikes converted inline
        for (int r = warp; r < 128; r += 8) {
            int bl = r >> 6, tl = r & 63, t = t0 + tl;
            uint2 z = make_uint2(0u, 0u);
            if (t < TT) {
                float4 v = reinterpret_cast<const float4*>(
                    spikes + ((size_t)t * BB + (b0 + bl)) * NI)[lane];
                unsigned h0 = (v.x > 0.5f) ? 0x3C00u : 0u;
                unsigned h1 = (v.y > 0.5f) ? 0x3C00u : 0u;
                unsigned h2 = (v.z > 0.5f) ? 0x3C00u : 0u;
                unsigned h3 = (v.w > 0.5f) ? 0x3C00u : 0u;
                z.x = h0 | (h1 << 16);
                z.y = h2 | (h3 << 16);
            }
            *reinterpret_cast<uint2*>(As + r * PA + lane * 4) = z;
        }
        // prefetch B for nb=0 into buf0
        for (int c = tid; c < 2048; c += 256) {
            int row = c >> 4, seg = (c & 15) * 8;
            const __half* src = (row < 64) ? (g_w1hi + (size_t)row * NI + seg)
                                           : (g_w1lo + (size_t)(row - 64) * NI + seg);
            CP_ASYNC16(sB0 + (uint32_t)((row * PA + seg) * 2), src);
        }
        CP_COMMIT();
        __syncthreads();            // A visible

        for (int nb = 0; nb < 8; nb++) {
            int n0 = nb * 64;
            uint32_t sBcur = (nb & 1) ? sB1 : sB0;
            if (nb < 7) {
                int nn0 = (nb + 1) * 64;
                uint32_t sBnx = (nb & 1) ? sB0 : sB1;
                for (int c = tid; c < 2048; c += 256) {
                    int row = c >> 4, seg = (c & 15) * 8;
                    const __half* src = (row < 64) ? (g_w1hi + (size_t)(nn0 + row) * NI + seg)
                                                   : (g_w1lo + (size_t)(nn0 + row - 64) * NI + seg);
                    CP_ASYNC16(sBnx + (uint32_t)((row * PA + seg) * 2), src);
                }
                CP_COMMIT();
                CP_WAIT1();
            } else {
                CP_WAIT0();
            }
            __syncthreads();        // current B visible

            float acc[2][2][4][4];
#pragma unroll
            for (int s = 0; s < 2; s++)
#pragma unroll
                for (int mt = 0; mt < 2; mt++)
#pragma unroll
                    for (int nt = 0; nt < 4; nt++)
#pragma unroll
                        for (int e = 0; e < 4; e++) acc[s][mt][nt][e] = 0.f;

#pragma unroll
            for (int ks = 0; ks < 8; ks++) {
                uint32_t a[2][4];
#pragma unroll
                for (int mt = 0; mt < 2; mt++) {
                    uint32_t addr = sA + (uint32_t)(((wm + mt * 16 + ra) * PA + ks * 16 + ca * 8) * 2);
                    asm volatile("ldmatrix.sync.aligned.m8n8.x4.shared.b16 {%0,%1,%2,%3}, [%4];"
                        : "=r"(a[mt][0]), "=r"(a[mt][1]), "=r"(a[mt][2]), "=r"(a[mt][3])
                        : "r"(addr));
                }
#pragma unroll
                for (int s = 0; s < 2; s++) {
                    uint32_t bf[2][4];
#pragma unroll
                    for (int hf = 0; hf < 2; hf++) {
                        uint32_t addr = sBcur + (uint32_t)(((s * 64 + wn + hf * 16 + rb) * PA + ks * 16 + cb) * 2);
                        asm volatile("ldmatrix.sync.aligned.m8n8.x4.shared.b16 {%0,%1,%2,%3}, [%4];"
                            : "=r"(bf[hf][0]), "=r"(bf[hf][1]), "=r"(bf[hf][2]), "=r"(bf[hf][3])
                            : "r"(addr));
                    }
#pragma unroll
                    for (int mt = 0; mt < 2; mt++)
#pragma unroll
                        for (int nt = 0; nt < 4; nt++) {
                            uint32_t bb0 = bf[nt >> 1][(nt & 1)];
                            uint32_t bb1 = bf[nt >> 1][(nt & 1) + 2];
                            asm volatile(
                                "mma.sync.aligned.m16n8k16.row.col.f32.f16.f16.f32 "
                                "{%0,%1,%2,%3}, {%4,%5,%6,%7}, {%8,%9}, {%0,%1,%2,%3};"
                                : "+f"(acc[s][mt][nt][0]), "+f"(acc[s][mt][nt][1]),
                                  "+f"(acc[s][mt][nt][2]), "+f"(acc[s][mt][nt][3])
                                : "r"(a[mt][0]), "r"(a[mt][1]), "r"(a[mt][2]), "r"(a[mt][3]),
                                  "r"(bb0), "r"(bb1));
                        }
                }
            }
            // combine limbs, write cur1 directly to gmem
#pragma unroll
            for (int mt = 0; mt < 2; mt++)
#pragma unroll
                for (int nt = 0; nt < 4; nt++) {
                    int row = wm + mt * 16 + (lane >> 2);
                    int col = n0 + wn + nt * 8 + (lane & 3) * 2;
                    float v0 = fmaf(acc[1][mt][nt][0], INV2048, acc[0][mt][nt][0]);
                    float v1 = fmaf(acc[1][mt][nt][1], INV2048, acc[0][mt][nt][1]);
                    float v2 = fmaf(acc[1][mt][nt][2], INV2048, acc[0][mt][nt][2]);
                    float v3 = fmaf(acc[1][mt][nt][3], INV2048, acc[0][mt][nt][3]);
                    {
                        int bl = row >> 6, tl = row & 63, t = t0 + tl;
                        if (t < TT)
                            *reinterpret_cast<float2*>(
                                g_cur1 + (size_t)t * BB * H1 + (size_t)(b0 + bl) * H1 + col) =
                                make_float2(v0, v1);
                    }
                    {
                        int r2 = row + 8;
                        int bl = r2 >> 6, tl = r2 & 63, t = t0 + tl;
                        if (t < TT)
                            *reinterpret_cast<float2*>(
                                g_cur1 + (size_t)t * BB * H1 + (size_t)(b0 + bl) * H1 + col) =
                                make_float2(v2, v3);
                    }
                }
            __syncthreads();        // B reads done before next prefetch / A rebuild
        }
    }
}

// ---------------- K1s: streaming LIF1 scan (thread per (b,h)) ----------------
// grid = 1024 (4 h-quarters per b), 128 threads
__global__ void __launch_bounds__(128) k1_scan(const float* __restrict__ b1) {
    int b = blockIdx.x >> 2;
    int h = (blockIdx.x & 3) * 128 + threadIdx.x;
    float bias = b1[h];
    const float* p = g_cur1 + (size_t)b * H1 + h;
    float mem = 0.f, spk = 0.f, cnt = 0.f;
    int word = h >> 5;
    bool lane0 = (threadIdx.x & 31) == 0;

#define STEP1(v, tt) { \
        mem = BETA1 * mem + ((v) + bias) - spk; \
        bool sp = mem > 1.f; \
        spk = sp ? 1.f : 0.f; cnt += spk; \
        unsigned m = __ballot_sync(0xffffffffu, sp); \
        if (lane0) g_bits[((tt) * BB + b) * NB1 + word] = m; }

    int t = 0;
    for (; t < 496; t += 8) {
        float v0 = p[(size_t)(t + 0) * BB * H1];
        float v1 = p[(size_t)(t + 1) * BB * H1];
        float v2 = p[(size_t)(t + 2) * BB * H1];
        float v3 = p[(size_t)(t + 3) * BB * H1];
        float v4 = p[(size_t)(t + 4) * BB * H1];
        float v5 = p[(size_t)(t + 5) * BB * H1];
        float v6 = p[(size_t)(t + 6) * BB * H1];
        float v7 = p[(size_t)(t + 7) * BB * H1];
        STEP1(v0, t + 0) STEP1(v1, t + 1) STEP1(v2, t + 2) STEP1(v3, t + 3)
        STEP1(v4, t + 4) STEP1(v5, t + 5) STEP1(v6, t + 6) STEP1(v7, t + 7)
    }
    {   // tail 4
        float v0 = p[(size_t)(t + 0) * BB * H1];
        float v1 = p[(size_t)(t + 1) * BB * H1];
        float v2 = p[(size_t)(t + 2) * BB * H1];
        float v3 = p[(size_t)(t + 3) * BB * H1];
        STEP1(v0, t + 0) STEP1(v1, t + 1) STEP1(v2, t + 2) STEP1(v3, t + 3)
    }
    g_s1cnt[b * H1 + h] = cnt;
}

// ---------------- K2a: sparse accumulate cur2, list built inline from bits ----
// grid = 148 blocks (4 g-quarters x 37), 1024 threads, warp per (t,b) pair
__global__ void __launch_bounds__(1024, 1) k2_acc(const float* __restrict__ W2) {
    extern __shared__ float sm[];           // 513*64 floats then per-warp lists
    unsigned* slist_all = (unsigned*)(sm + 513 * 64);
    int q   = blockIdx.x & 3;
    int blk = blockIdx.x >> 2;
    int tid = threadIdx.x;

    const float4* W4 = reinterpret_cast<const float4*>(W2 + (size_t)q * 64 * H1);
    for (int c = tid; c < 64 * 128; c += 1024) {
        int g  = c >> 7;
        int hb = (c & 127) * 4;
        float4 w = W4[c];
        sm[(hb + 0) * 64 + g] = w.x;
        sm[(hb + 1) * 64 + g] = w.y;
        sm[(hb + 2) * 64 + g] = w.z;
        sm[(hb + 3) * 64 + g] = w.w;
    }
    for (int c = tid; c < 64; c += 1024) sm[512 * 64 + c] = 0.f;
    __syncthreads();

    int warp = tid >> 5, lane = tid & 31;
    int wg = blk * 32 + warp;
    const char* smb = (const char*)sm;
    unsigned* sl = slist_all + warp * 544;
    unsigned lane8 = (unsigned)lane << 3;

    unsigned nextbits = (lane < NB1) ? g_bits[(size_t)wg * NB1 + lane] : 0u;

    for (int p = wg; p < TT * BB; p += 1184) {
        unsigned w16 = nextbits;
        int pn = p + 1184;
        if (pn < TT * BB)
            nextbits = (lane < NB1) ? g_bits[(size_t)pn * NB1 + lane] : 0u;

        int c = __popc(w16);
        int pre = c;
#pragma unroll
        for (int d = 1; d < 16; d <<= 1) {
            int v = __shfl_up_sync(0xffffffffu, pre, d);
            if (lane >= d) pre += v;
        }
        int total = __shfl_sync(0xffffffffu, pre, 15);
        int o = pre - c;
        if (lane < NB1) {
            unsigned bits = w16;
            while (bits) {
                int i = __ffs(bits) - 1;
                sl[o++] = (unsigned)(lane * 32 + i) << 8;   // pre-shifted row byte offset
                bits &= bits - 1;
            }
        }
        int ntot = (total + 7) & ~7;
        for (int k = total + lane; k < ntot; k += 32) sl[k] = (unsigned)H1 << 8;  // zero row
        __syncwarp();

        const uint4* lp = reinterpret_cast<const uint4*>(sl);
        float ax = 0.f, ay = 0.f, bx = 0.f, by = 0.f;
        int nc = ntot >> 3;
#define GATH2(e, AX, AY) { \
            float2 v = *(const float2*)(smb + (e) + lane8); \
            AX += v.x; AY += v.y; }
        for (int cc = 0; cc < nc; cc++) {
            uint4 e0 = lp[2 * cc];
            uint4 e1 = lp[2 * cc + 1];
            GATH2(e0.x, ax, ay) GATH2(e0.y, bx, by)
            GATH2(e0.z, ax, ay) GATH2(e0.w, bx, by)
            GATH2(e1.x, ax, ay) GATH2(e1.y, bx, by)
            GATH2(e1.z, ax, ay) GATH2(e1.w, bx, by)
        }
        float2 r = make_float2(ax + bx, ay + by);
        *(float2*)(g_cur2 + (size_t)p * H2 + q * 64 + lane * 2) = r;
        __syncwarp();
    }
}

// ---------------- K2s: streaming LIF2 scan ----------------
// grid = 512 (2 g-halves per b), 128 threads
__global__ void __launch_bounds__(128) k2_scan(const float* __restrict__ b2) {
    int b = blockIdx.x >> 1;
    int g = (blockIdx.x & 1) * 128 + threadIdx.x;
    float bias = b2[g];
    const float* p = g_cur2 + (size_t)b * H2 + g;
    float mem = 0.f, spk = 0.f, msum = 0.f, scnt = 0.f;

#define STEP2(v) { \
        mem = BETA2 * mem + ((v) + bias) - spk; \
        msum += mem; \
        bool sp = mem > 1.f; \
        spk = sp ? 1.f : 0.f; scnt += spk; }

    int t = 0;
    for (; t < 496; t += 8) {
        float v0 = p[(size_t)(t + 0) * BB * H2];
        float v1 = p[(size_t)(t + 1) * BB * H2];
        float v2 = p[(size_t)(t + 2) * BB * H2];
        float v3 = p[(size_t)(t + 3) * BB * H2];
        float v4 = p[(size_t)(t + 4) * BB * H2];
        float v5 = p[(size_t)(t + 5) * BB * H2];
        float v6 = p[(size_t)(t + 6) * BB * H2];
        float v7 = p[(size_t)(t + 7) * BB * H2];
        STEP2(v0) STEP2(v1) STEP2(v2) STEP2(v3)
        STEP2(v4) STEP2(v5) STEP2(v6) STEP2(v7)
    }
    {
        float v0 = p[(size_t)(t + 0) * BB * H2];
        float v1 = p[(size_t)(t + 1) * BB * H2];
        float v2 = p[(size_t)(t + 2) * BB * H2];
        float v3 = p[(size_t)(t + 3) * BB * H2];
        STEP2(v0) STEP2(v1) STEP2(v2) STEP2(v3)
    }
    g_m2sum[b * H2 + g] = msum;
    g_s2cnt[b * H2 + g] = scnt;
}

// ---------------- K3: readout + means ----------------
__global__ void k_readout(const float* __restrict__ Wr, const float* __restrict__ br,
                          const float* __restrict__ Ws, const float* __restrict__ bs,
                          float* __restrict__ out) {
    __shared__ float red[256];
    int blk = blockIdx.x;
    int tid = threadIdx.x;
    const float inv_t = 1.f / (float)TT;

    if (blk < BB) {
        int b = blk;
        float a0 = 0.f, a1 = 0.f;
        for (int j = tid; j < H2; j += 128) {
            float x = g_m2sum[b * H2 + j] * inv_t;
            a0 += x * Wr[j];
            a1 += x * Wr[H2 + j];
        }
        for (int j = tid; j < H1; j += 128) {
            float x = g_s1cnt[b * H1 + j] * inv_t;
            a0 += x * Ws[j];
            a1 += x * Ws[H1 + j];
        }
        red[tid] = a0; red[128 + tid] = a1;
        __syncthreads();
        for (int s = 64; s > 0; s >>= 1) {
            if (tid < s) { red[tid] += red[tid + s]; red[128 + tid] += red[128 + tid + s]; }
            __syncthreads();
        }
        if (tid == 0) {
            out[b * 2 + 0] = red[0]   + br[0] + bs[0];
            out[b * 2 + 1] = red[128] + br[1] + bs[1];
        }
    } else if (blk == BB) {
        float a = 0.f;
        for (int j = tid; j < BB * H1; j += 128) a += g_s1cnt[j];
        red[tid] = a; __syncthreads();
        for (int s = 64; s > 0; s >>= 1) { if (tid < s) red[tid] += red[tid + s]; __syncthreads(); }
        if (tid == 0) out[512] = red[0] / (float)((long long)TT * BB * H1);
    } else {
        float a = 0.f;
        for (int j = tid; j < BB * H2; j += 128) a += g_s2cnt[j];
        red[tid] = a; __syncthreads();
        for (int s = 64; s > 0; s >>= 1) { if (tid < s) red[tid] += red[tid + s]; __syncthreads(); }
        if (tid == 0) out[513] = red[0] / (float)((long long)TT * BB * H2);
    }
}

// ---------------- launch ----------------
extern "C" void kernel_launch(void* const* d_in, const int* in_sizes, int n_in,
                              void* d_out, int out_size) {
    const float* spikes = (const float*)d_in[0];
    const float* W1 = (const float*)d_in[1];
    const float* b1 = (const float*)d_in[2];
    const float* W2 = (const float*)d_in[3];
    const float* b2 = (const float*)d_in[4];
    const float* Wr = (const float*)d_in[5];
    const float* br = (const float*)d_in[6];
    const float* Ws = (const float*)d_in[7];
    const float* bs = (const float*)d_in[8];
    float* out = (float*)d_out;

    const int smem2 = 513 * 64 * 4 + 32 * 544 * 4;   // 200960 B
    cudaFuncSetAttribute(k1_mm,  cudaFuncAttributeMaxDynamicSharedMemorySize, SMEM1);
    cudaFuncSetAttribute(k2_acc, cudaFuncAttributeMaxDynamicSharedMemorySize, smem2);

    k_wprep<<<(H1 * NI + 255) / 256, 256>>>(W1);
    k1_mm<<<K1GRID, 256, SMEM1>>>(spikes);
    k1_scan<<<1024, 128>>>(b1);
    k2_acc<<<148, 1024, smem2>>>(W2);
    k2_scan<<<512, 128>>>(b2);
    k_readout<<<BB + 2, 128>>>(Wr, br, Ws, bs, out);
}

// round 16
// speedup vs baseline: 1.0517x; 1.0517x over previous
#include <cuda_runtime.h>
#include <cuda_fp16.h>
#include <cstdint>

#define TT 500
#define BB 256
#define NI 128
#define H1 512
#define H2 256
#define NB1 16

#define BETA1 0.81873075307798182f
#define BETA2 0.90483741803595952f
#define INV2048 4.8828125e-4f

// ---------------- device scratch (static, no allocations) ----------------
__device__ __align__(16) __half g_w1hi[H1 * NI];
__device__ __align__(16) __half g_w1lo[H1 * NI];
__device__ unsigned  g_bits[TT * BB * NB1];           // spk1 bitmasks
__device__ float     g_s1cnt[BB * H1];
__device__ float     g_m2sum[BB * H2];
__device__ float     g_s2cnt[BB * H2];
__device__ float     g_cur1[(size_t)TT * BB * H1];    // dense currents layer1 (262 MB)
__device__ float     g_cur2[(size_t)TT * BB * H2];

#define CP_ASYNC16(dst, src) asm volatile("cp.async.cg.shared.global [%0], [%1], 16;" :: "r"(dst), "l"(src))
#define CP_COMMIT()          asm volatile("cp.async.commit_group;")
#define CP_WAIT1()           asm volatile("cp.async.wait_group 1;")
#define CP_WAIT0()           asm volatile("cp.async.wait_group 0;")

// ---------------- K0: W1 -> hi/lo fp16 split ----------------
__global__ void k_wprep(const float* __restrict__ W1) {
    int i = blockIdx.x * blockDim.x + threadIdx.x;
    if (i >= H1 * NI) return;
    float w = W1[i];
    __half hi = __float2half_rn(w);
    float lo = (w - __half2float(hi)) * 2048.f;
    g_w1hi[i] = hi;
    g_w1lo[i] = __float2half_rn(lo);
}

// ---------------- K1mm: dense fp16-MMA GEMM -> cur1 ----------------
// grid = 1024 (128 batch-pairs x 8 t-chunks of 64), 256 threads (8 warps 32x32)
// M=128 rows (2b x 64t), per nb: N=64 cols, B rows 0-63 hi / 64-127 lo.
// smem: A 128x136 h | B[2] 128x136 h  = 104448 B -> 2 blocks/SM
#define PA 136
#define SM_A   0
#define SM_B0  34816
#define SM_B1  69632
#define SMEM1  104448

__global__ void __launch_bounds__(256, 2) k1_mm(const float* __restrict__ spikes) {
    extern __shared__ char smc[];
    __half* As = (__half*)(smc + SM_A);

    int tid  = threadIdx.x;
    int lane = tid & 31;
    int warp = tid >> 5;
    int bp    = blockIdx.x >> 3;
    int chunk = blockIdx.x & 7;
    int b0 = bp * 2;
    int t0 = chunk * 64;

    int wm = (warp & 3) * 32;
    int wn = (warp >> 2) * 32;
    int ra = lane & 15, ca = lane >> 4;
    int rb = (lane & 7) + ((lane >> 3) & 1) * 8;
    int cb = (lane >> 4) * 8;

    uint32_t sA  = (uint32_t)__cvta_generic_to_shared(As);
    uint32_t sB0 = (uint32_t)__cvta_generic_to_shared(smc + SM_B0);
    uint32_t sB1 = (uint32_t)__cvta_generic_to_shared(smc + SM_B1);

    // build A: 128 rows (2b x 64t) x 128 halves, spikes converted inline
    for (int r = warp; r < 128; r += 8) {
        int bl = r >> 6, tl = r & 63, t = t0 + tl;
        uint2 z = make_uint2(0u, 0u);
        if (t < TT) {
            float4 v = reinterpret_cast<const float4*>(
                spikes + ((size_t)t * BB + (b0 + bl)) * NI)[lane];
            unsigned h0 = (v.x > 0.5f) ? 0x3C00u : 0u;
            unsigned h1 = (v.y > 0.5f) ? 0x3C00u : 0u;
            unsigned h2 = (v.z > 0.5f) ? 0x3C00u : 0u;
            unsigned h3 = (v.w > 0.5f) ? 0x3C00u : 0u;
            z.x = h0 | (h1 << 16);
            z.y = h2 | (h3 << 16);
        }
        *reinterpret_cast<uint2*>(As + r * PA + lane * 4) = z;
    }
    // prefetch B for nb=0 into buf0
    for (int c = tid; c < 2048; c += 256) {
        int row = c >> 4, seg = (c & 15) * 8;
        const __half* src = (row < 64) ? (g_w1hi + (size_t)row * NI + seg)
                                       : (g_w1lo + (size_t)(row - 64) * NI + seg);
        CP_ASYNC16(sB0 + (uint32_t)((row * PA + seg) * 2), src);
    }
    CP_COMMIT();
    __syncthreads();            // A visible

    for (int nb = 0; nb < 8; nb++) {
        int n0 = nb * 64;
        uint32_t sBcur = (nb & 1) ? sB1 : sB0;
        if (nb < 7) {
            int nn0 = (nb + 1) * 64;
            uint32_t sBnx = (nb & 1) ? sB0 : sB1;
            for (int c = tid; c < 2048; c += 256) {
                int row = c >> 4, seg = (c & 15) * 8;
                const __half* src = (row < 64) ? (g_w1hi + (size_t)(nn0 + row) * NI + seg)
                                               : (g_w1lo + (size_t)(nn0 + row - 64) * NI + seg);
                CP_ASYNC16(sBnx + (uint32_t)((row * PA + seg) * 2), src);
            }
            CP_COMMIT();
            CP_WAIT1();
        } else {
            CP_WAIT0();
        }
        __syncthreads();        // current B visible

        float acc[2][2][4][4];
#pragma unroll
        for (int s = 0; s < 2; s++)
#pragma unroll
            for (int mt = 0; mt < 2; mt++)
#pragma unroll
                for (int nt = 0; nt < 4; nt++)
#pragma unroll
                    for (int e = 0; e < 4; e++) acc[s][mt][nt][e] = 0.f;

#pragma unroll
        for (int ks = 0; ks < 8; ks++) {
            uint32_t a[2][4];
#pragma unroll
            for (int mt = 0; mt < 2; mt++) {
                uint32_t addr = sA + (uint32_t)(((wm + mt * 16 + ra) * PA + ks * 16 + ca * 8) * 2);
                asm volatile("ldmatrix.sync.aligned.m8n8.x4.shared.b16 {%0,%1,%2,%3}, [%4];"
                    : "=r"(a[mt][0]), "=r"(a[mt][1]), "=r"(a[mt][2]), "=r"(a[mt][3])
                    : "r"(addr));
            }
#pragma unroll
            for (int s = 0; s < 2; s++) {
                uint32_t bf[2][4];
#pragma unroll
                for (int hf = 0; hf < 2; hf++) {
                    uint32_t addr = sBcur + (uint32_t)(((s * 64 + wn + hf * 16 + rb) * PA + ks * 16 + cb) * 2);
                    asm volatile("ldmatrix.sync.aligned.m8n8.x4.shared.b16 {%0,%1,%2,%3}, [%4];"
                        : "=r"(bf[hf][0]), "=r"(bf[hf][1]), "=r"(bf[hf][2]), "=r"(bf[hf][3])
                        : "r"(addr));
                }
#pragma unroll
                for (int mt = 0; mt < 2; mt++)
#pragma unroll
                    for (int nt = 0; nt < 4; nt++) {
                        uint32_t bb0 = bf[nt >> 1][(nt & 1)];
                        uint32_t bb1 = bf[nt >> 1][(nt & 1) + 2];
                        asm volatile(
                            "mma.sync.aligned.m16n8k16.row.col.f32.f16.f16.f32 "
                            "{%0,%1,%2,%3}, {%4,%5,%6,%7}, {%8,%9}, {%0,%1,%2,%3};"
                            : "+f"(acc[s][mt][nt][0]), "+f"(acc[s][mt][nt][1]),
                              "+f"(acc[s][mt][nt][2]), "+f"(acc[s][mt][nt][3])
                            : "r"(a[mt][0]), "r"(a[mt][1]), "r"(a[mt][2]), "r"(a[mt][3]),
                              "r"(bb0), "r"(bb1));
                    }
            }
        }
        // combine limbs, write cur1 directly to gmem
#pragma unroll
        for (int mt = 0; mt < 2; mt++)
#pragma unroll
            for (int nt = 0; nt < 4; nt++) {
                int row = wm + mt * 16 + (lane >> 2);
                int col = n0 + wn + nt * 8 + (lane & 3) * 2;
                float v0 = fmaf(acc[1][mt][nt][0], INV2048, acc[0][mt][nt][0]);
                float v1 = fmaf(acc[1][mt][nt][1], INV2048, acc[0][mt][nt][1]);
                float v2 = fmaf(acc[1][mt][nt][2], INV2048, acc[0][mt][nt][2]);
                float v3 = fmaf(acc[1][mt][nt][3], INV2048, acc[0][mt][nt][3]);
                {
                    int bl = row >> 6, tl = row & 63, t = t0 + tl;
                    if (t < TT)
                        *reinterpret_cast<float2*>(
                            g_cur1 + (size_t)t * BB * H1 + (size_t)(b0 + bl) * H1 + col) =
                            make_float2(v0, v1);
                }
                {
                    int r2 = row + 8;
                    int bl = r2 >> 6, tl = r2 & 63, t = t0 + tl;
                    if (t < TT)
                        *reinterpret_cast<float2*>(
                            g_cur1 + (size_t)t * BB * H1 + (size_t)(b0 + bl) * H1 + col) =
                            make_float2(v2, v3);
                }
            }
        __syncthreads();        // all reads of current B done before next prefetch reuses it
    }
}

// ---------------- K1s: streaming LIF1 scan (thread per (b,h)) ----------------
// grid = 512 (b-halves), 256 threads
__global__ void __launch_bounds__(256) k1_scan(const float* __restrict__ b1) {
    int b = blockIdx.x >> 1;
    int h = (blockIdx.x & 1) * 256 + threadIdx.x;
    float bias = b1[h];
    const float* p = g_cur1 + (size_t)b * H1 + h;
    float mem = 0.f, spk = 0.f, cnt = 0.f;
    int word = h >> 5;
    bool lane0 = (threadIdx.x & 31) == 0;

#define STEP1(v, tt) { \
        mem = BETA1 * mem + ((v) + bias) - spk; \
        bool sp = mem > 1.f; \
        spk = sp ? 1.f : 0.f; cnt += spk; \
        unsigned m = __ballot_sync(0xffffffffu, sp); \
        if (lane0) g_bits[((tt) * BB + b) * NB1 + word] = m; }

    int t = 0;
    for (; t < 496; t += 8) {
        float v0 = p[(size_t)(t + 0) * BB * H1];
        float v1 = p[(size_t)(t + 1) * BB * H1];
        float v2 = p[(size_t)(t + 2) * BB * H1];
        float v3 = p[(size_t)(t + 3) * BB * H1];
        float v4 = p[(size_t)(t + 4) * BB * H1];
        float v5 = p[(size_t)(t + 5) * BB * H1];
        float v6 = p[(size_t)(t + 6) * BB * H1];
        float v7 = p[(size_t)(t + 7) * BB * H1];
        STEP1(v0, t + 0) STEP1(v1, t + 1) STEP1(v2, t + 2) STEP1(v3, t + 3)
        STEP1(v4, t + 4) STEP1(v5, t + 5) STEP1(v6, t + 6) STEP1(v7, t + 7)
    }
    {   // tail 4
        float v0 = p[(size_t)(t + 0) * BB * H1];
        float v1 = p[(size_t)(t + 1) * BB * H1];
        float v2 = p[(size_t)(t + 2) * BB * H1];
        float v3 = p[(size_t)(t + 3) * BB * H1];
        STEP1(v0, t + 0) STEP1(v1, t + 1) STEP1(v2, t + 2) STEP1(v3, t + 3)
    }
    g_s1cnt[b * H1 + h] = cnt;
}

// ---------------- K2a: sparse accumulate cur2, list built inline from bits ----
// grid = 148 blocks (4 g-quarters x 37), 1024 threads, warp per (t,b) pair
// W2 quarter stored PLAIN: sm[h*64 + g] (rows 256 B); gather addr = (h<<8) + lane*8
// -> conflict-free gather with 4 issue slots/index; transpose store conflicts
//    are one-shot and amortized. Next pair's bitmask is prefetched.
__global__ void __launch_bounds__(1024, 1) k2_acc(const float* __restrict__ W2) {
    extern __shared__ float sm[];           // 513*64 floats then per-warp lists
    unsigned* slist_all = (unsigned*)(sm + 513 * 64);
    int q   = blockIdx.x & 3;
    int blk = blockIdx.x >> 2;
    int tid = threadIdx.x;

    const float4* W4 = reinterpret_cast<const float4*>(W2 + (size_t)q * 64 * H1);
    for (int c = tid; c < 64 * 128; c += 1024) {
        int g  = c >> 7;
        int hb = (c & 127) * 4;
        float4 w = W4[c];
        sm[(hb + 0) * 64 + g] = w.x;
        sm[(hb + 1) * 64 + g] = w.y;
        sm[(hb + 2) * 64 + g] = w.z;
        sm[(hb + 3) * 64 + g] = w.w;
    }
    for (int c = tid; c < 64; c += 1024) sm[512 * 64 + c] = 0.f;
    __syncthreads();

    int warp = tid >> 5, lane = tid & 31;
    int wg = blk * 32 + warp;
    const char* smb = (const char*)sm;
    unsigned* sl = slist_all + warp * 544;
    unsigned lane8 = (unsigned)lane << 3;

    unsigned nextbits = (lane < NB1) ? g_bits[(size_t)wg * NB1 + lane] : 0u;

    for (int p = wg; p < TT * BB; p += 1184) {
        unsigned w16 = nextbits;
        int pn = p + 1184;
        if (pn < TT * BB)
            nextbits = (lane < NB1) ? g_bits[(size_t)pn * NB1 + lane] : 0u;

        int c = __popc(w16);
        int pre = c;
#pragma unroll
        for (int d = 1; d < 16; d <<= 1) {
            int v = __shfl_up_sync(0xffffffffu, pre, d);
            if (lane >= d) pre += v;
        }
        int total = __shfl_sync(0xffffffffu, pre, 15);
        int o = pre - c;
        if (lane < NB1) {
            unsigned bits = w16;
            while (bits) {
                int i = __ffs(bits) - 1;
                sl[o++] = (unsigned)(lane * 32 + i) << 8;   // pre-shifted row byte offset
                bits &= bits - 1;
            }
        }
        int ntot = (total + 7) & ~7;
        for (int k = total + lane; k < ntot; k += 32) sl[k] = (unsigned)H1 << 8;  // zero row
        __syncwarp();

        const uint4* lp = reinterpret_cast<const uint4*>(sl);
        float ax = 0.f, ay = 0.f, bx = 0.f, by = 0.f;
        int nc = ntot >> 3;
#define GATH2(e, AX, AY) { \
            float2 v = *(const float2*)(smb + (e) + lane8); \
            AX += v.x; AY += v.y; }
        for (int cc = 0; cc < nc; cc++) {
            uint4 e0 = lp[2 * cc];
            uint4 e1 = lp[2 * cc + 1];
            GATH2(e0.x, ax, ay) GATH2(e0.y, bx, by)
            GATH2(e0.z, ax, ay) GATH2(e0.w, bx, by)
            GATH2(e1.x, ax, ay) GATH2(e1.y, bx, by)
            GATH2(e1.z, ax, ay) GATH2(e1.w, bx, by)
        }
        float2 r = make_float2(ax + bx, ay + by);
        *(float2*)(g_cur2 + (size_t)p * H2 + q * 64 + lane * 2) = r;
        __syncwarp();
    }
}

// ---------------- K2s: streaming LIF2 scan ----------------
__global__ void __launch_bounds__(256) k2_scan(const float* __restrict__ b2) {
    int b = blockIdx.x;
    int g = threadIdx.x;
    float bias = b2[g];
    const float* p = g_cur2 + (size_t)b * H2 + g;
    float mem = 0.f, spk = 0.f, msum = 0.f, scnt = 0.f;

#define STEP2(v) { \
        mem = BETA2 * mem + ((v) + bias) - spk; \
        msum += mem; \
        bool sp = mem > 1.f; \
        spk = sp ? 1.f : 0.f; scnt += spk; }

    int t = 0;
    for (; t < 496; t += 8) {
        float v0 = p[(size_t)(t + 0) * BB * H2];
        float v1 = p[(size_t)(t + 1) * BB * H2];
        float v2 = p[(size_t)(t + 2) * BB * H2];
        float v3 = p[(size_t)(t + 3) * BB * H2];
        float v4 = p[(size_t)(t + 4) * BB * H2];
        float v5 = p[(size_t)(t + 5) * BB * H2];
        float v6 = p[(size_t)(t + 6) * BB * H2];
        float v7 = p[(size_t)(t + 7) * BB * H2];
        STEP2(v0) STEP2(v1) STEP2(v2) STEP2(v3)
        STEP2(v4) STEP2(v5) STEP2(v6) STEP2(v7)
    }
    {
        float v0 = p[(size_t)(t + 0) * BB * H2];
        float v1 = p[(size_t)(t + 1) * BB * H2];
        float v2 = p[(size_t)(t + 2) * BB * H2];
        float v3 = p[(size_t)(t + 3) * BB * H2];
        STEP2(v0) STEP2(v1) STEP2(v2) STEP2(v3)
    }
    g_m2sum[b * H2 + g] = msum;
    g_s2cnt[b * H2 + g] = scnt;
}

// ---------------- K3: readout + means ----------------
__global__ void k_readout(const float* __restrict__ Wr, const float* __restrict__ br,
                          const float* __restrict__ Ws, const float* __restrict__ bs,
                          float* __restrict__ out) {
    __shared__ float red[256];
    int blk = blockIdx.x;
    int tid = threadIdx.x;
    const float inv_t = 1.f / (float)TT;

    if (blk < BB) {
        int b = blk;
        float a0 = 0.f, a1 = 0.f;
        for (int j = tid; j < H2; j += 128) {
            float x = g_m2sum[b * H2 + j] * inv_t;
            a0 += x * Wr[j];
            a1 += x * Wr[H2 + j];
        }
        for (int j = tid; j < H1; j += 128) {
            float x = g_s1cnt[b * H1 + j] * inv_t;
            a0 += x * Ws[j];
            a1 += x * Ws[H1 + j];
        }
        red[tid] = a0; red[128 + tid] = a1;
        __syncthreads();
        for (int s = 64; s > 0; s >>= 1) {
            if (tid < s) { red[tid] += red[tid + s]; red[128 + tid] += red[128 + tid + s]; }
            __syncthreads();
        }
        if (tid == 0) {
            out[b * 2 + 0] = red[0]   + br[0] + bs[0];
            out[b * 2 + 1] = red[128] + br[1] + bs[1];
        }
    } else if (blk == BB) {
        float a = 0.f;
        for (int j = tid; j < BB * H1; j += 128) a += g_s1cnt[j];
        red[tid] = a; __syncthreads();
        for (int s = 64; s > 0; s >>= 1) { if (tid < s) red[tid] += red[tid + s]; __syncthreads(); }
        if (tid == 0) out[512] = red[0] / (float)((long long)TT * BB * H1);
    } else {
        float a = 0.f;
        for (int j = tid; j < BB * H2; j += 128) a += g_s2cnt[j];
        red[tid] = a; __syncthreads();
        for (int s = 64; s > 0; s >>= 1) { if (tid < s) red[tid] += red[tid + s]; __syncthreads(); }
        if (tid == 0) out[513] = red[0] / (float)((long long)TT * BB * H2);
    }
}

// ---------------- launch ----------------
extern "C" void kernel_launch(void* const* d_in, const int* in_sizes, int n_in,
                              void* d_out, int out_size) {
    const float* spikes = (const float*)d_in[0];
    const float* W1 = (const float*)d_in[1];
    const float* b1 = (const float*)d_in[2];
    const float* W2 = (const float*)d_in[3];
    const float* b2 = (const float*)d_in[4];
    const float* Wr = (const float*)d_in[5];
    const float* br = (const float*)d_in[6];
    const float* Ws = (const float*)d_in[7];
    const float* bs = (const float*)d_in[8];
    float* out = (float*)d_out;

    const int smem2 = 513 * 64 * 4 + 32 * 544 * 4;   // 200960 B
    cudaFuncSetAttribute(k1_mm,  cudaFuncAttributeMaxDynamicSharedMemorySize, SMEM1);
    cudaFuncSetAttribute(k2_acc, cudaFuncAttributeMaxDynamicSharedMemorySize, smem2);

    k_wprep<<<(H1 * NI + 255) / 256, 256>>>(W1);
    k1_mm<<<1024, 256, SMEM1>>>(spikes);
    k1_scan<<<512, 256>>>(b1);
    k2_acc<<<148, 1024, smem2>>>(W2);
    k2_scan<<<256, 256>>>(b2);
    k_readout<<<BB + 2, 128>>>(Wr, br, Ws, bs, out);
}

// round 17
// speedup vs baseline: 1.0766x; 1.0237x over previous
#include <cuda_runtime.h>
#include <cuda_fp16.h>
#include <cstdint>

#define TT 500
#define BB 256
#define NI 128
#define H1 512
#define H2 256
#define NB1 16

#define BETA1 0.81873075307798182f
#define BETA2 0.90483741803595952f
#define INV2048 4.8828125e-4f

// ---------------- device scratch (static, no allocations) ----------------
__device__ __align__(16) __half g_w1hi[H1 * NI];
__device__ __align__(16) __half g_w1lo[H1 * NI];
__device__ unsigned  g_bits[TT * BB * NB1];           // spk1 bitmasks
__device__ float     g_s1cnt[BB * H1];
__device__ float     g_m2sum[BB * H2];
__device__ float     g_s2cnt[BB * H2];
__device__ float     g_cur1[(size_t)TT * BB * H1];    // dense currents layer1 (262 MB)
__device__ float     g_cur2[(size_t)TT * BB * H2];

#define CP_ASYNC16(dst, src) asm volatile("cp.async.cg.shared.global [%0], [%1], 16;" :: "r"(dst), "l"(src))
#define CP_COMMIT()          asm volatile("cp.async.commit_group;")
#define CP_WAIT1()           asm volatile("cp.async.wait_group 1;")
#define CP_WAIT0()           asm volatile("cp.async.wait_group 0;")

// ---------------- K0: W1 -> hi/lo fp16 split ----------------
__global__ void k_wprep(const float* __restrict__ W1) {
    int i = blockIdx.x * blockDim.x + threadIdx.x;
    if (i >= H1 * NI) return;
    float w = W1[i];
    __half hi = __float2half_rn(w);
    float lo = (w - __half2float(hi)) * 2048.f;
    g_w1hi[i] = hi;
    g_w1lo[i] = __float2half_rn(lo);
}

// ---------------- K1mm: dense fp16-MMA GEMM -> cur1 ----------------
// grid = 1024 (128 batch-pairs x 8 t-chunks of 64), 256 threads (8 warps 32x32)
// M=128 rows (2b x 64t), per nb: N=64 cols, B rows 0-63 hi / 64-127 lo.
// smem: A 128x136 h | B[2] 128x136 h  = 104448 B -> 2 blocks/SM
#define PA 136
#define SM_A   0
#define SM_B0  34816
#define SM_B1  69632
#define SMEM1  104448

__global__ void __launch_bounds__(256, 2) k1_mm(const float* __restrict__ spikes) {
    extern __shared__ char smc[];
    __half* As = (__half*)(smc + SM_A);

    int tid  = threadIdx.x;
    int lane = tid & 31;
    int warp = tid >> 5;
    int bp    = blockIdx.x >> 3;
    int chunk = blockIdx.x & 7;
    int b0 = bp * 2;
    int t0 = chunk * 64;

    int wm = (warp & 3) * 32;
    int wn = (warp >> 2) * 32;
    int ra = lane & 15, ca = lane >> 4;
    int rb = (lane & 7) + ((lane >> 3) & 1) * 8;
    int cb = (lane >> 4) * 8;

    uint32_t sA  = (uint32_t)__cvta_generic_to_shared(As);
    uint32_t sB0 = (uint32_t)__cvta_generic_to_shared(smc + SM_B0);
    uint32_t sB1 = (uint32_t)__cvta_generic_to_shared(smc + SM_B1);

    // build A: 128 rows (2b x 64t) x 128 halves, spikes converted inline
    for (int r = warp; r < 128; r += 8) {
        int bl = r >> 6, tl = r & 63, t = t0 + tl;
        uint2 z = make_uint2(0u, 0u);
        if (t < TT) {
            float4 v = reinterpret_cast<const float4*>(
                spikes + ((size_t)t * BB + (b0 + bl)) * NI)[lane];
            unsigned h0 = (v.x > 0.5f) ? 0x3C00u : 0u;
            unsigned h1 = (v.y > 0.5f) ? 0x3C00u : 0u;
            unsigned h2 = (v.z > 0.5f) ? 0x3C00u : 0u;
            unsigned h3 = (v.w > 0.5f) ? 0x3C00u : 0u;
            z.x = h0 | (h1 << 16);
            z.y = h2 | (h3 << 16);
        }
        *reinterpret_cast<uint2*>(As + r * PA + lane * 4) = z;
    }
    // prefetch B for nb=0 into buf0
    for (int c = tid; c < 2048; c += 256) {
        int row = c >> 4, seg = (c & 15) * 8;
        const __half* src = (row < 64) ? (g_w1hi + (size_t)row * NI + seg)
                                       : (g_w1lo + (size_t)(row - 64) * NI + seg);
        CP_ASYNC16(sB0 + (uint32_t)((row * PA + seg) * 2), src);
    }
    CP_COMMIT();
    __syncthreads();            // A visible

    for (int nb = 0; nb < 8; nb++) {
        int n0 = nb * 64;
        uint32_t sBcur = (nb & 1) ? sB1 : sB0;
        if (nb < 7) {
            int nn0 = (nb + 1) * 64;
            uint32_t sBnx = (nb & 1) ? sB0 : sB1;
            for (int c = tid; c < 2048; c += 256) {
                int row = c >> 4, seg = (c & 15) * 8;
                const __half* src = (row < 64) ? (g_w1hi + (size_t)(nn0 + row) * NI + seg)
                                               : (g_w1lo + (size_t)(nn0 + row - 64) * NI + seg);
                CP_ASYNC16(sBnx + (uint32_t)((row * PA + seg) * 2), src);
            }
            CP_COMMIT();
            CP_WAIT1();
        } else {
            CP_WAIT0();
        }
        __syncthreads();        // current B visible

        float acc[2][2][4][4];
#pragma unroll
        for (int s = 0; s < 2; s++)
#pragma unroll
            for (int mt = 0; mt < 2; mt++)
#pragma unroll
                for (int nt = 0; nt < 4; nt++)
#pragma unroll
                    for (int e = 0; e < 4; e++) acc[s][mt][nt][e] = 0.f;

#pragma unroll
        for (int ks = 0; ks < 8; ks++) {
            uint32_t a[2][4];
#pragma unroll
            for (int mt = 0; mt < 2; mt++) {
                uint32_t addr = sA + (uint32_t)(((wm + mt * 16 + ra) * PA + ks * 16 + ca * 8) * 2);
                asm volatile("ldmatrix.sync.aligned.m8n8.x4.shared.b16 {%0,%1,%2,%3}, [%4];"
                    : "=r"(a[mt][0]), "=r"(a[mt][1]), "=r"(a[mt][2]), "=r"(a[mt][3])
                    : "r"(addr));
            }
#pragma unroll
            for (int s = 0; s < 2; s++) {
                uint32_t bf[2][4];
#pragma unroll
                for (int hf = 0; hf < 2; hf++) {
                    uint32_t addr = sBcur + (uint32_t)(((s * 64 + wn + hf * 16 + rb) * PA + ks * 16 + cb) * 2);
                    asm volatile("ldmatrix.sync.aligned.m8n8.x4.shared.b16 {%0,%1,%2,%3}, [%4];"
                        : "=r"(bf[hf][0]), "=r"(bf[hf][1]), "=r"(bf[hf][2]), "=r"(bf[hf][3])
                        : "r"(addr));
                }
#pragma unroll
                for (int mt = 0; mt < 2; mt++)
#pragma unroll
                    for (int nt = 0; nt < 4; nt++) {
                        uint32_t bb0 = bf[nt >> 1][(nt & 1)];
                        uint32_t bb1 = bf[nt >> 1][(nt & 1) + 2];
                        asm volatile(
                            "mma.sync.aligned.m16n8k16.row.col.f32.f16.f16.f32 "
                            "{%0,%1,%2,%3}, {%4,%5,%6,%7}, {%8,%9}, {%0,%1,%2,%3};"
                            : "+f"(acc[s][mt][nt][0]), "+f"(acc[s][mt][nt][1]),
                              "+f"(acc[s][mt][nt][2]), "+f"(acc[s][mt][nt][3])
                            : "r"(a[mt][0]), "r"(a[mt][1]), "r"(a[mt][2]), "r"(a[mt][3]),
                              "r"(bb0), "r"(bb1));
                    }
            }
        }
        // combine limbs, write cur1 directly to gmem
#pragma unroll
        for (int mt = 0; mt < 2; mt++)
#pragma unroll
            for (int nt = 0; nt < 4; nt++) {
                int row = wm + mt * 16 + (lane >> 2);
                int col = n0 + wn + nt * 8 + (lane & 3) * 2;
                float v0 = fmaf(acc[1][mt][nt][0], INV2048, acc[0][mt][nt][0]);
                float v1 = fmaf(acc[1][mt][nt][1], INV2048, acc[0][mt][nt][1]);
                float v2 = fmaf(acc[1][mt][nt][2], INV2048, acc[0][mt][nt][2]);
                float v3 = fmaf(acc[1][mt][nt][3], INV2048, acc[0][mt][nt][3]);
                {
                    int bl = row >> 6, tl = row & 63, t = t0 + tl;
                    if (t < TT)
                        *reinterpret_cast<float2*>(
                            g_cur1 + (size_t)t * BB * H1 + (size_t)(b0 + bl) * H1 + col) =
                            make_float2(v0, v1);
                }
                {
                    int r2 = row + 8;
                    int bl = r2 >> 6, tl = r2 & 63, t = t0 + tl;
                    if (t < TT)
                        *reinterpret_cast<float2*>(
                            g_cur1 + (size_t)t * BB * H1 + (size_t)(b0 + bl) * H1 + col) =
                            make_float2(v2, v3);
                }
            }
        __syncthreads();        // all reads of current B done before next prefetch reuses it
    }
}

// ---------------- K1s: streaming LIF1 scan (thread per (b,h)) ----------------
// grid = 512 (b-halves), 256 threads, 16-deep load batching
__global__ void __launch_bounds__(256) k1_scan(const float* __restrict__ b1) {
    int b = blockIdx.x >> 1;
    int h = (blockIdx.x & 1) * 256 + threadIdx.x;
    float bias = b1[h];
    const float* p = g_cur1 + (size_t)b * H1 + h;
    float mem = 0.f, spk = 0.f, cnt = 0.f;
    int word = h >> 5;
    bool lane0 = (threadIdx.x & 31) == 0;

#define STEP1(v, tt) { \
        mem = BETA1 * mem + ((v) + bias) - spk; \
        bool sp = mem > 1.f; \
        spk = sp ? 1.f : 0.f; cnt += spk; \
        unsigned m = __ballot_sync(0xffffffffu, sp); \
        if (lane0) g_bits[((tt) * BB + b) * NB1 + word] = m; }

    int t = 0;
    for (; t < 496; t += 16) {
        float v[16];
#pragma unroll
        for (int k = 0; k < 16; k++)
            v[k] = p[(size_t)(t + k) * BB * H1];
#pragma unroll
        for (int k = 0; k < 16; k++)
            STEP1(v[k], t + k)
    }
    {   // tail 4
        float v0 = p[(size_t)(t + 0) * BB * H1];
        float v1 = p[(size_t)(t + 1) * BB * H1];
        float v2 = p[(size_t)(t + 2) * BB * H1];
        float v3 = p[(size_t)(t + 3) * BB * H1];
        STEP1(v0, t + 0) STEP1(v1, t + 1) STEP1(v2, t + 2) STEP1(v3, t + 3)
    }
    g_s1cnt[b * H1 + h] = cnt;
}

// ---------------- K2a: sparse accumulate cur2, list built inline from bits ----
// grid = 148 blocks (4 g-quarters x 37), 1024 threads, warp per (t,b) pair
// W2 quarter stored PLAIN: sm[h*64 + g] (rows 256 B); gather addr = (h<<8) + lane*8
__global__ void __launch_bounds__(1024, 1) k2_acc(const float* __restrict__ W2) {
    extern __shared__ float sm[];           // 513*64 floats then per-warp lists
    unsigned* slist_all = (unsigned*)(sm + 513 * 64);
    int q   = blockIdx.x & 3;
    int blk = blockIdx.x >> 2;
    int tid = threadIdx.x;

    const float4* W4 = reinterpret_cast<const float4*>(W2 + (size_t)q * 64 * H1);
    for (int c = tid; c < 64 * 128; c += 1024) {
        int g  = c >> 7;
        int hb = (c & 127) * 4;
        float4 w = W4[c];
        sm[(hb + 0) * 64 + g] = w.x;
        sm[(hb + 1) * 64 + g] = w.y;
        sm[(hb + 2) * 64 + g] = w.z;
        sm[(hb + 3) * 64 + g] = w.w;
    }
    for (int c = tid; c < 64; c += 1024) sm[512 * 64 + c] = 0.f;
    __syncthreads();

    int warp = tid >> 5, lane = tid & 31;
    int wg = blk * 32 + warp;
    const char* smb = (const char*)sm;
    unsigned* sl = slist_all + warp * 544;
    unsigned lane8 = (unsigned)lane << 3;

    unsigned nextbits = (lane < NB1) ? g_bits[(size_t)wg * NB1 + lane] : 0u;

    for (int p = wg; p < TT * BB; p += 1184) {
        unsigned w16 = nextbits;
        int pn = p + 1184;
        if (pn < TT * BB)
            nextbits = (lane < NB1) ? g_bits[(size_t)pn * NB1 + lane] : 0u;

        int c = __popc(w16);
        int pre = c;
#pragma unroll
        for (int d = 1; d < 16; d <<= 1) {
            int v = __shfl_up_sync(0xffffffffu, pre, d);
            if (lane >= d) pre += v;
        }
        int total = __shfl_sync(0xffffffffu, pre, 15);
        int o = pre - c;
        if (lane < NB1) {
            unsigned bits = w16;
            while (bits) {
                int i = __ffs(bits) - 1;
                sl[o++] = (unsigned)(lane * 32 + i) << 8;   // pre-shifted row byte offset
                bits &= bits - 1;
            }
        }
        int ntot = (total + 7) & ~7;
        for (int k = total + lane; k < ntot; k += 32) sl[k] = (unsigned)H1 << 8;  // zero row
        __syncwarp();

        const uint4* lp = reinterpret_cast<const uint4*>(sl);
        float ax = 0.f, ay = 0.f, bx = 0.f, by = 0.f;
        int nc = ntot >> 3;
#define GATH2(e, AX, AY) { \
            float2 v = *(const float2*)(smb + (e) + lane8); \
            AX += v.x; AY += v.y; }
        for (int cc = 0; cc < nc; cc++) {
            uint4 e0 = lp[2 * cc];
            uint4 e1 = lp[2 * cc + 1];
            GATH2(e0.x, ax, ay) GATH2(e0.y, bx, by)
            GATH2(e0.z, ax, ay) GATH2(e0.w, bx, by)
            GATH2(e1.x, ax, ay) GATH2(e1.y, bx, by)
            GATH2(e1.z, ax, ay) GATH2(e1.w, bx, by)
        }
        float2 r = make_float2(ax + bx, ay + by);
        *(float2*)(g_cur2 + (size_t)p * H2 + q * 64 + lane * 2) = r;
        __syncwarp();
    }
}

// ---------------- K2s: streaming LIF2 scan ----------------
// grid = 256 (b), 256 threads, 16-deep load batching
__global__ void __launch_bounds__(256) k2_scan(const float* __restrict__ b2) {
    int b = blockIdx.x;
    int g = threadIdx.x;
    float bias = b2[g];
    const float* p = g_cur2 + (size_t)b * H2 + g;
    float mem = 0.f, spk = 0.f, msum = 0.f, scnt = 0.f;

#define STEP2(v) { \
        mem = BETA2 * mem + ((v) + bias) - spk; \
        msum += mem; \
        bool sp = mem > 1.f; \
        spk = sp ? 1.f : 0.f; scnt += spk; }

    int t = 0;
    for (; t < 496; t += 16) {
        float v[16];
#pragma unroll
        for (int k = 0; k < 16; k++)
            v[k] = p[(size_t)(t + k) * BB * H2];
#pragma unroll
        for (int k = 0; k < 16; k++)
            STEP2(v[k])
    }
    {
        float v0 = p[(size_t)(t + 0) * BB * H2];
        float v1 = p[(size_t)(t + 1) * BB * H2];
        float v2 = p[(size_t)(t + 2) * BB * H2];
        float v3 = p[(size_t)(t + 3) * BB * H2];
        STEP2(v0) STEP2(v1) STEP2(v2) STEP2(v3)
    }
    g_m2sum[b * H2 + g] = msum;
    g_s2cnt[b * H2 + g] = scnt;
}

// ---------------- K3: readout + means ----------------
__global__ void k_readout(const float* __restrict__ Wr, const float* __restrict__ br,
                          const float* __restrict__ Ws, const float* __restrict__ bs,
                          float* __restrict__ out) {
    __shared__ float red[256];
    int blk = blockIdx.x;
    int tid = threadIdx.x;
    const float inv_t = 1.f / (float)TT;

    if (blk < BB) {
        int b = blk;
        float a0 = 0.f, a1 = 0.f;
        for (int j = tid; j < H2; j += 128) {
            float x = g_m2sum[b * H2 + j] * inv_t;
            a0 += x * Wr[j];
            a1 += x * Wr[H2 + j];
        }
        for (int j = tid; j < H1; j += 128) {
            float x = g_s1cnt[b * H1 + j] * inv_t;
            a0 += x * Ws[j];
            a1 += x * Ws[H1 + j];
        }
        red[tid] = a0; red[128 + tid] = a1;
        __syncthreads();
        for (int s = 64; s > 0; s >>= 1) {
            if (tid < s) { red[tid] += red[tid + s]; red[128 + tid] += red[128 + tid + s]; }
            __syncthreads();
        }
        if (tid == 0) {
            out[b * 2 + 0] = red[0]   + br[0] + bs[0];
            out[b * 2 + 1] = red[128] + br[1] + bs[1];
        }
    } else if (blk == BB) {
        float a = 0.f;
        for (int j = tid; j < BB * H1; j += 128) a += g_s1cnt[j];
        red[tid] = a; __syncthreads();
        for (int s = 64; s > 0; s >>= 1) { if (tid < s) red[tid] += red[tid + s]; __syncthreads(); }
        if (tid == 0) out[512] = red[0] / (float)((long long)TT * BB * H1);
    } else {
        float a = 0.f;
        for (int j = tid; j < BB * H2; j += 128) a += g_s2cnt[j];
        red[tid] = a; __syncthreads();
        for (int s = 64; s > 0; s >>= 1) { if (tid < s) red[tid] += red[tid + s]; __syncthreads(); }
        if (tid == 0) out[513] = red[0] / (float)((long long)TT * BB * H2);
    }
}

// ---------------- launch ----------------
extern "C" void kernel_launch(void* const* d_in, const int* in_sizes, int n_in,
                              void* d_out, int out_size) {
    const float* spikes = (const float*)d_in[0];
    const float* W1 = (const float*)d_in[1];
    const float* b1 = (const float*)d_in[2];
    const float* W2 = (const float*)d_in[3];
    const float* b2 = (const float*)d_in[4];
    const float* Wr = (const float*)d_in[5];
    const float* br = (const float*)d_in[6];
    const float* Ws = (const float*)d_in[7];
    const float* bs = (const float*)d_in[8];
    float* out = (float*)d_out;

    const int smem2 = 513 * 64 * 4 + 32 * 544 * 4;   // 200960 B
    cudaFuncSetAttribute(k1_mm,  cudaFuncAttributeMaxDynamicSharedMemorySize, SMEM1);
    cudaFuncSetAttribute(k2_acc, cudaFuncAttributeMaxDynamicSharedMemorySize, smem2);

    k_wprep<<<(H1 * NI + 255) / 256, 256>>>(W1);
    k1_mm<<<1024, 256, SMEM1>>>(spikes);
    k1_scan<<<512, 256>>>(b1);
    k2_acc<<<148, 1024, smem2>>>(W2);
    k2_scan<<<256, 256>>>(b2);
    k_readout<<<BB + 2, 128>>>(Wr, br, Ws, bs, out);
}